// round 12
// baseline (speedup 1.0000x reference)
#include <cuda_runtime.h>
#include <cuda_fp16.h>
#include <math.h>
#include <stdint.h>

#define Bsz 2
#define Ssz 2048
#define Hsz 16
#define Msz 4096

// fp16 scratch: XH 8MB | WT 18MB | QKV 48MB | OB 16MB | TB 16MB
#define OFF_XH  0ull
#define OFF_WT  8388608ull
#define OFF_QKV 27262976ull
#define OFF_OB  77594624ull
#define OFF_TB  94371840ull
__device__ __align__(1024) unsigned char g_scratch[111149056ull];

// ---------------------------------------------------------------------------
// helpers
// ---------------------------------------------------------------------------
__device__ __forceinline__ uint32_t cvta_smem(const void* p) {
    uint32_t a;
    asm("{ .reg .u64 t; cvta.to.shared.u64 t, %1; cvt.u32.u64 %0, t; }"
        : "=r"(a) : "l"(p));
    return a;
}
__device__ __forceinline__ void cp16(uint32_t dst, const void* src) {
    asm volatile("cp.async.cg.shared.global [%0], [%1], 16;" :: "r"(dst), "l"(src));
}
__device__ __forceinline__ void cp_commit() { asm volatile("cp.async.commit_group;"); }
template <int N>
__device__ __forceinline__ void cp_wait() { asm volatile("cp.async.wait_group %0;" :: "n"(N)); }

__device__ __forceinline__ uint32_t f2h2(float lo, float hi) {
    uint32_t r;
    asm("cvt.rn.f16x2.f32 %0, %2, %1;" : "=r"(r) : "f"(lo), "f"(hi));
    return r;
}
__device__ __forceinline__ float2 h2f2(uint32_t u) {
    __half2 h = *reinterpret_cast<__half2*>(&u);
    return __half22float2(h);
}
__device__ __forceinline__ float ex2f(float x) {
    float r;
    asm("ex2.approx.f32 %0, %1;" : "=f"(r) : "f"(x));
    return r;
}
__device__ __forceinline__ uint32_t ex2h2(uint32_t x) {
    uint32_t r;
    asm("ex2.approx.f16x2 %0, %1;" : "=r"(r) : "r"(x));
    return r;
}

// mma m16n8k16 fp16 in, fp32 accum
__device__ __forceinline__ void mma16(float c[4], const uint32_t a[4],
                                      uint32_t b0, uint32_t b1) {
    asm volatile(
        "mma.sync.aligned.m16n8k16.row.col.f32.f16.f16.f32 "
        "{%0,%1,%2,%3}, {%4,%5,%6,%7}, {%8,%9}, {%0,%1,%2,%3};"
        : "+f"(c[0]), "+f"(c[1]), "+f"(c[2]), "+f"(c[3])
        : "r"(a[0]), "r"(a[1]), "r"(a[2]), "r"(a[3]), "r"(b0), "r"(b1));
}
__device__ __forceinline__ void ldm_x4(uint32_t r[4], uint32_t addr) {
    asm volatile("ldmatrix.sync.aligned.m8n8.x4.shared.b16 {%0,%1,%2,%3}, [%4];"
        : "=r"(r[0]), "=r"(r[1]), "=r"(r[2]), "=r"(r[3]) : "r"(addr));
}
__device__ __forceinline__ void ldm_x4t(uint32_t r[4], uint32_t addr) {
    asm volatile("ldmatrix.sync.aligned.m8n8.x4.trans.shared.b16 {%0,%1,%2,%3}, [%4];"
        : "=r"(r[0]), "=r"(r[1]), "=r"(r[2]), "=r"(r[3]) : "r"(addr));
}

struct PtrsW { const float* p[9]; };
struct PtrsB { const float* p[6]; };
struct HPtrs6 { const __half* p[6]; };

// ---------------------------------------------------------------------------
// prep: z<9: transpose+convert weight z to [n][k] fp16; z==9: convert x fp16
// ---------------------------------------------------------------------------
__global__ __launch_bounds__(256)
void prep_all(PtrsW src, const float4* __restrict__ xin,
              uint32_t* __restrict__ wdst, uint4* __restrict__ xdst)
{
    const int z = blockIdx.z;
    if (z == 9) {
        int bid = blockIdx.y * 32 + blockIdx.x;
        int tid = threadIdx.y * 32 + threadIdx.x;
#pragma unroll
        for (int i = 0; i < 2; i++) {
            int idx = bid * 512 + tid + i * 256;   // 524288 total
            float4 v0 = xin[2 * idx], v1 = xin[2 * idx + 1];
            uint4 o;
            o.x = f2h2(v0.x, v0.y); o.y = f2h2(v0.z, v0.w);
            o.z = f2h2(v1.x, v1.y); o.w = f2h2(v1.z, v1.w);
            xdst[idx] = o;
        }
        return;
    }
    __shared__ float tsm[32][33];
    const float* W = src.p[z];
    uint32_t* out = wdst + (size_t)z * (1024 * 512);
    const int bx = blockIdx.x * 32, by = blockIdx.y * 32;
    const int x = threadIdx.x, y = threadIdx.y;
    for (int i = y; i < 32; i += 8)
        tsm[i][x] = W[(size_t)(by + i) * 1024 + bx + x];
    __syncthreads();
    int tid = y * 32 + x;
#pragma unroll
    for (int s = 0; s < 2; s++) {
        int idx = tid + s * 256;
        int row = idx >> 4, p = idx & 15;
        out[(size_t)(bx + row) * 512 + (by >> 1) + p] =
            f2h2(tsm[2 * p][row], tsm[2 * p + 1][row]);
    }
}

// ---------------------------------------------------------------------------
// fp16 GEMM, CTA 128x128, BK=64, 4 warps (warp tile 64x64), 2-stage cp.async,
// 128 threads, 2 CTAs/SM. VAR 0/1: ldmatrix. VAR 2: scalar + fused diff.
// ---------------------------------------------------------------------------
#define AW 36
#define BW 36
#define A_U (128 * AW)   // 4608 u32
#define B_U (128 * BW)   // 4608 u32

template <int VAR>
__global__ __launch_bounds__(128, 2)
void gemm_h(const __half* __restrict__ A, HPtrs6 Bp, PtrsB biasP,
            void* __restrict__ Cout, int N, int lda, int ldc,
            const float* __restrict__ lambda_param,
            const unsigned* __restrict__ layer_idx_bits)
{
    constexpr int A_ST = (VAR == 2) ? 2 * A_U : A_U;
    constexpr int STG = A_ST + B_U;
    extern __shared__ uint32_t smu[];
    const uint32_t sbase = cvta_smem(smu);

    const int tid = threadIdx.x;
    const int lane = tid & 31;
    const int g = lane >> 2, t = lane & 3;
    const int lrow = lane & 7, lsel = lane >> 3;
    const int wid = tid >> 5;
    const int wm = wid >> 1, wn = wid & 1;       // 2 x 2 warp grid, 64x64 tiles
    const int m0 = blockIdx.y * 128, n0 = blockIdx.x * 128;
    const int j = n0 >> 10, nn = n0 & 1023;
    const int aoffr = (VAR == 1) ? (j << 10) : 0;

    float lam = 0.f;
    if (VAR == 2) {
        unsigned bits = *layer_idx_bits;
        float lf = (bits < 10000u) ? (float)bits : __uint_as_float(bits);
        float e = __expf(-0.3f * fmaxf(lf - 1.0f, 0.0f));
        lam = fminf(fmaxf((0.8f - 0.6f * e) * lambda_param[0], 0.1f), 0.9f);
    }

    const __half* Bj = Bp.p[j];
    float c[4][8][4] = {};

    const uint32_t aoff = (uint32_t)((wm * 64 + ((lsel & 1) ? 8 : 0) + lrow) * AW
                                     + ((lsel >> 1) ? 4 : 0)) * 4u;
    const uint32_t boff = (uint32_t)((wn * 64 + ((lsel >> 1) ? 8 : 0) + lrow) * BW
                                     + ((lsel & 1) ? 4 : 0)) * 4u;

    auto loadTile = [&](int stg, int kt) {
        uint32_t sa = sbase + (uint32_t)(stg * STG) * 4u;
        uint32_t sb = sa + (uint32_t)A_ST * 4u;
#pragma unroll
        for (int i = 0; i < 8; i++) {
            int idx = tid + i * 128;
            int row = idx >> 3, ch = idx & 7;
            const __half* src = A + (size_t)(m0 + row) * lda + aoffr + kt * 64 + ch * 8;
            cp16(sa + (uint32_t)(row * AW + ch * 4) * 4u, src);
            if (VAR == 2)
                cp16(sa + (uint32_t)(A_U + row * AW + ch * 4) * 4u, src + 1024);
        }
#pragma unroll
        for (int i = 0; i < 8; i++) {
            int idx = tid + i * 128;
            int row = idx >> 3, ch = idx & 7;
            cp16(sb + (uint32_t)(row * BW + ch * 4) * 4u,
                 Bj + (size_t)(nn + row) * 1024 + kt * 64 + ch * 8);
        }
        cp_commit();
    };

    const int T = 16;   // 1024 / 64
    loadTile(0, 0);

    for (int kt = 0; kt < T; kt++) {
        const int stg = kt & 1;
        cp_wait<0>();
        __syncthreads();
        if (kt + 1 < T) loadTile(stg ^ 1, kt + 1);

        if (VAR == 2) {
            const uint32_t* Au = smu + stg * STG;
            const uint32_t* Bu = Au + A_ST;
#pragma unroll
            for (int kf = 0; kf < 4; kf++) {
                uint32_t a[4][4];
#pragma unroll
                for (int mf = 0; mf < 4; mf++) {
                    int rb = wm * 64 + mf * 16;
#pragma unroll
                    for (int q = 0; q < 4; q++) {
                        int r = rb + g + ((q & 1) ? 8 : 0);
                        int kp = kf * 8 + t + ((q >> 1) ? 4 : 0);
                        float2 fu = h2f2(Au[r * AW + kp]);
                        float2 fv = h2f2(Au[A_U + r * AW + kp]);
                        a[mf][q] = f2h2(fmaf(-lam, fv.x, fu.x), fmaf(-lam, fv.y, fu.y));
                    }
                }
#pragma unroll
                for (int nf = 0; nf < 8; nf++) {
                    int n = wn * 64 + nf * 8 + g;
                    uint32_t b0 = Bu[n * BW + kf * 8 + t];
                    uint32_t b1 = Bu[n * BW + kf * 8 + 4 + t];
#pragma unroll
                    for (int mf = 0; mf < 4; mf++)
                        mma16(c[mf][nf], a[mf], b0, b1);
                }
            }
        } else {
            uint32_t aS = sbase + (uint32_t)(stg * STG) * 4u + aoff;
            uint32_t bS = sbase + (uint32_t)(stg * STG + A_ST) * 4u + boff;
#pragma unroll
            for (int kf = 0; kf < 4; kf++) {
                uint32_t a[4][4], bq[4][4];
#pragma unroll
                for (int mf = 0; mf < 4; mf++)
                    ldm_x4(a[mf], aS + (uint32_t)(mf * 16 * AW) * 4u + kf * 32u);
#pragma unroll
                for (int i = 0; i < 4; i++)
                    ldm_x4(bq[i], bS + (uint32_t)(i * 16 * BW) * 4u + kf * 32u);
#pragma unroll
                for (int i = 0; i < 4; i++)
#pragma unroll
                    for (int mf = 0; mf < 4; mf++) {
                        mma16(c[mf][2 * i],     a[mf], bq[i][0], bq[i][1]);
                        mma16(c[mf][2 * i + 1], a[mf], bq[i][2], bq[i][3]);
                    }
            }
        }
    }

    const float* bb = biasP.p[j] + nn;
#pragma unroll
    for (int mf = 0; mf < 4; mf++) {
        int r0 = m0 + wm * 64 + mf * 16 + g;
#pragma unroll
        for (int nf = 0; nf < 8; nf++) {
            int cl = wn * 64 + nf * 8 + 2 * t;
            float bv0 = bb[cl], bv1 = bb[cl + 1];
            float v00 = c[mf][nf][0] + bv0, v01 = c[mf][nf][1] + bv1;
            float v10 = c[mf][nf][2] + bv0, v11 = c[mf][nf][3] + bv1;
            if (VAR == 2) {
                float* C = (float*)Cout;
                *(float2*)(C + (size_t)r0 * ldc + n0 + cl) = make_float2(v00, v01);
                *(float2*)(C + (size_t)(r0 + 8) * ldc + n0 + cl) = make_float2(v10, v11);
            } else {
                uint32_t* C = (uint32_t*)Cout;
                int lp = ldc >> 1;
                C[(size_t)r0 * lp + ((n0 + cl) >> 1)] = f2h2(v00, v01);
                C[(size_t)(r0 + 8) * lp + ((n0 + cl) >> 1)] = f2h2(v10, v11);
            }
        }
    }
}

// ---------------------------------------------------------------------------
// fp16 flash attention: 4 warps x 32 q-rows, 128 q-rows/CTA, 3 CTAs/SM.
// S-phase shares K ldm across both m-frags; softmax+PV per m-frag (V re-read)
// to keep register peak under the 170-reg / 3-CTA budget.
// ---------------------------------------------------------------------------
#define KWu 36
#define KSTGu (64 * KWu)
#define ATT_SMEM (4 * KSTGu * 4)   // 36864 B

__global__ __launch_bounds__(128, 3)
void flash_h(const __half* __restrict__ QKV, __half* __restrict__ OB)
{
    extern __shared__ uint32_t smu[];
    const uint32_t sbase = cvta_smem(smu);
    const uint32_t sK = sbase;
    const uint32_t sV = sbase + (uint32_t)(2 * KSTGu) * 4u;

    const int tid = threadIdx.x;
    const int w = tid >> 5, lane = tid & 31;
    const int g = lane >> 2, t = lane & 3;
    const int sel = lane >> 3, r8 = lane & 7;
    const int b = blockIdx.y >> 4, h = blockIdx.y & 15, z = blockIdx.z;
    const int q0 = blockIdx.x * 128;
    const size_t ld = 6144;

    const size_t base = (size_t)b * Ssz * ld + (size_t)z * 3072 + h * 64;
    const __half* Kg = QKV + base + 1024;
    const __half* Vg = QKV + base + 2048;

    // Q scale = log2(e)/8 : softmax runs in exp2 domain
    const __half2 scq = __float2half2_rn(0.18033688f);
    uint32_t qf[2][4][4];
#pragma unroll
    for (int mf = 0; mf < 2; mf++) {
#pragma unroll
        for (int q = 0; q < 4; q++) {
            int row = q0 + w * 32 + mf * 16 + g + ((q & 1) ? 8 : 0);
            const __half2* Q2 = (const __half2*)QKV + ((base + (size_t)row * ld) >> 1);
#pragma unroll
            for (int kf = 0; kf < 4; kf++) {
                __half2 v = __hmul2(Q2[kf * 8 + t + ((q >> 1) ? 4 : 0)], scq);
                qf[mf][kf][q] = *(uint32_t*)&v;
            }
        }
    }

    float o[2][8][4] = {};
    float lc[2][4] = {};
    float mm[2][2] = { {-1e30f, -1e30f}, {-1e30f, -1e30f} };
    const uint32_t ONE2 = 0x3C003C00u;

    auto loadKV = [&](int buf, int tile) {
#pragma unroll
        for (int i = 0; i < 4; i++) {
            int idx = tid + i * 128;
            int row = idx >> 3, ch = idx & 7;
            size_t off = (size_t)(tile * 64 + row) * ld + ch * 8;
            cp16(sK + (uint32_t)(buf * KSTGu + row * KWu + ch * 4) * 4u, Kg + off);
            cp16(sV + (uint32_t)(buf * KSTGu + row * KWu + ch * 4) * 4u, Vg + off);
        }
        cp_commit();
    };

    const int NT = Ssz / 64;
    loadKV(0, 0);

    const int rowB = (sel >= 2) ? 8 : 0, colB = (sel & 1) ? 4 : 0;
    const int rowA = (sel & 1) ? 8 : 0, colA = (sel >= 2) ? 4 : 0;

    for (int tile = 0; tile < NT; tile++) {
        const int buf = tile & 1;
        cp_wait<0>();
        __syncthreads();
        if (tile + 1 < NT) loadKV(buf ^ 1, tile + 1);

        const uint32_t sKb = sK + (uint32_t)(buf * KSTGu) * 4u;
        const uint32_t sVb = sV + (uint32_t)(buf * KSTGu) * 4u;

        // S = Q K^T for both m-frags (K frags shared)
        float s[2][8][4] = {};
#pragma unroll
        for (int kf = 0; kf < 4; kf++) {
#pragma unroll
            for (int np = 0; np < 4; np++) {
                uint32_t kb[4];
                ldm_x4(kb, sKb + (uint32_t)((np * 16 + rowB + r8) * KWu + kf * 8 + colB) * 4u);
                mma16(s[0][2 * np],     qf[0][kf], kb[0], kb[1]);
                mma16(s[0][2 * np + 1], qf[0][kf], kb[2], kb[3]);
                mma16(s[1][2 * np],     qf[1][kf], kb[0], kb[1]);
                mma16(s[1][2 * np + 1], qf[1][kf], kb[2], kb[3]);
            }
        }

        // per m-frag: softmax -> P frags -> l-MMA -> PV (V re-read per mf)
#pragma unroll
        for (int mf = 0; mf < 2; mf++) {
            float tmax0 = -1e30f, tmax1 = -1e30f;
#pragma unroll
            for (int nf = 0; nf < 8; nf++) {
                tmax0 = fmaxf(tmax0, fmaxf(s[mf][nf][0], s[mf][nf][1]));
                tmax1 = fmaxf(tmax1, fmaxf(s[mf][nf][2], s[mf][nf][3]));
            }
            tmax0 = fmaxf(tmax0, __shfl_xor_sync(0xffffffffu, tmax0, 1));
            tmax0 = fmaxf(tmax0, __shfl_xor_sync(0xffffffffu, tmax0, 2));
            tmax1 = fmaxf(tmax1, __shfl_xor_sync(0xffffffffu, tmax1, 1));
            tmax1 = fmaxf(tmax1, __shfl_xor_sync(0xffffffffu, tmax1, 2));

            float mn0 = fmaxf(mm[mf][0], tmax0), mn1 = fmaxf(mm[mf][1], tmax1);

            uint32_t pa[4][4];
#pragma unroll
            for (int nf = 0; nf < 8; nf++) {
                uint32_t p01 = ex2h2(f2h2(s[mf][nf][0] - mn0, s[mf][nf][1] - mn0));
                uint32_t p23 = ex2h2(f2h2(s[mf][nf][2] - mn1, s[mf][nf][3] - mn1));
                pa[nf >> 1][(nf & 1) * 2 + 0] = p01;
                pa[nf >> 1][(nf & 1) * 2 + 1] = p23;
            }

            bool moved = !__all_sync(0xffffffffu, (mn0 == mm[mf][0]) & (mn1 == mm[mf][1]));
            if (moved) {
                float al0 = ex2f(mm[mf][0] - mn0), al1 = ex2f(mm[mf][1] - mn1);
                lc[mf][0] *= al0; lc[mf][2] *= al1;
#pragma unroll
                for (int nf = 0; nf < 8; nf++) {
                    o[mf][nf][0] *= al0; o[mf][nf][1] *= al0;
                    o[mf][nf][2] *= al1; o[mf][nf][3] *= al1;
                }
            }
            mm[mf][0] = mn0; mm[mf][1] = mn1;

#pragma unroll
            for (int kf = 0; kf < 4; kf++)
                mma16(lc[mf], pa[kf], ONE2, ONE2);

#pragma unroll
            for (int kf = 0; kf < 4; kf++) {
#pragma unroll
                for (int np = 0; np < 4; np++) {
                    uint32_t vb[4];
                    ldm_x4t(vb, sVb + (uint32_t)((kf * 16 + rowA + r8) * KWu + np * 8 + colA) * 4u);
                    mma16(o[mf][2 * np],     pa[kf], vb[0], vb[1]);
                    mma16(o[mf][2 * np + 1], pa[kf], vb[2], vb[3]);
                }
            }
        }
    }

    uint32_t* O2 = (uint32_t*)OB;
#pragma unroll
    for (int mf = 0; mf < 2; mf++) {
        float inv0 = 1.f / lc[mf][0], inv1 = 1.f / lc[mf][2];
        int row = q0 + w * 32 + mf * 16 + g;
        size_t rb0 = (size_t)(b * Ssz + row) * 1024 + z * 512 + h * 32;
        size_t rb1 = rb0 + 8 * 1024;
#pragma unroll
        for (int nf = 0; nf < 8; nf++) {
            O2[rb0 + nf * 4 + t] = f2h2(o[mf][nf][0] * inv0, o[mf][nf][1] * inv0);
            O2[rb1 + nf * 4 + t] = f2h2(o[mf][nf][2] * inv1, o[mf][nf][3] * inv1);
        }
    }
}

// ---------------------------------------------------------------------------
extern "C" void kernel_launch(void* const* d_in, const int* in_sizes, int n_in,
                              void* d_out, int out_size)
{
    const float*    x            = (const float*)d_in[0];
    const unsigned* layer_idx    = (const unsigned*)d_in[1];
    const float*    lambda_param = (const float*)d_in[2];

    const float *Wq1, *bq1, *Wk1, *bk1, *Wv1, *bv1, *Wo1, *bo1;
    const float *Wq2, *bq2, *Wk2, *bk2, *Wv2, *bv2, *Wo2, *bo2;

    bool sig_order = (in_sizes[4] < 100000);
    if (!sig_order) {
        Wq1 = (const float*)d_in[3];  Wk1 = (const float*)d_in[4];
        Wv1 = (const float*)d_in[5];  Wo1 = (const float*)d_in[6];
        bq1 = (const float*)d_in[7];  bk1 = (const float*)d_in[8];
        bv1 = (const float*)d_in[9];  bo1 = (const float*)d_in[10];
        Wq2 = (const float*)d_in[11]; Wk2 = (const float*)d_in[12];
        Wv2 = (const float*)d_in[13]; Wo2 = (const float*)d_in[14];
        bq2 = (const float*)d_in[15]; bk2 = (const float*)d_in[16];
        bv2 = (const float*)d_in[17]; bo2 = (const float*)d_in[18];
    } else {
        Wq1 = (const float*)d_in[3];  bq1 = (const float*)d_in[4];
        Wk1 = (const float*)d_in[5];  bk1 = (const float*)d_in[6];
        Wv1 = (const float*)d_in[7];  bv1 = (const float*)d_in[8];
        Wo1 = (const float*)d_in[9];  bo1 = (const float*)d_in[10];
        Wq2 = (const float*)d_in[11]; bq2 = (const float*)d_in[12];
        Wk2 = (const float*)d_in[13]; bk2 = (const float*)d_in[14];
        Wv2 = (const float*)d_in[15]; bv2 = (const float*)d_in[16];
        Wo2 = (const float*)d_in[17]; bo2 = (const float*)d_in[18];
    }
    const float* Wp = (const float*)d_in[19];
    const float* bp = (const float*)d_in[20];

    unsigned char* sc = nullptr;
    cudaGetSymbolAddress((void**)&sc, g_scratch);
    __half* XH  = (__half*)(sc + OFF_XH);
    __half* WT  = (__half*)(sc + OFF_WT);
    __half* QKV = (__half*)(sc + OFF_QKV);
    __half* OB  = (__half*)(sc + OFF_OB);
    __half* TB  = (__half*)(sc + OFF_TB);

    const int SMEM01 = 2 * (A_U + B_U) * 4;       // 73728
    const int SMEM2  = 2 * (2 * A_U + B_U) * 4;   // 110592

    cudaFuncSetAttribute(gemm_h<0>, cudaFuncAttributeMaxDynamicSharedMemorySize, SMEM01);
    cudaFuncSetAttribute(gemm_h<1>, cudaFuncAttributeMaxDynamicSharedMemorySize, SMEM01);
    cudaFuncSetAttribute(gemm_h<2>, cudaFuncAttributeMaxDynamicSharedMemorySize, SMEM2);
    cudaFuncSetAttribute(flash_h,   cudaFuncAttributeMaxDynamicSharedMemorySize, ATT_SMEM);

    PtrsW srcW = {{ Wq1, Wk1, Wv1, Wq2, Wk2, Wv2, Wo1, Wo2, Wp }};
    prep_all<<<dim3(32, 32, 10), dim3(32, 8)>>>(srcW, (const float4*)x,
                                                (uint32_t*)WT, (uint4*)XH);

    HPtrs6 wqkv = {{ WT + 0ull * 1048576, WT + 1ull * 1048576, WT + 2ull * 1048576,
                     WT + 3ull * 1048576, WT + 4ull * 1048576, WT + 5ull * 1048576 }};
    PtrsB bqkv = {{ bq1, bk1, bv1, bq2, bk2, bv2 }};
    gemm_h<0><<<dim3(48, 32), 128, SMEM01>>>(XH, wqkv, bqkv, QKV, 6144, 1024, 6144,
                                             nullptr, nullptr);

    flash_h<<<dim3(Ssz / 128, Bsz * Hsz, 2), 128, ATT_SMEM>>>(QKV, OB);

    HPtrs6 wwo = {{ WT + 6ull * 1048576, WT + 7ull * 1048576, nullptr, nullptr, nullptr, nullptr }};
    PtrsB bwo = {{ bo1, bo2, nullptr, nullptr, nullptr, nullptr }};
    gemm_h<1><<<dim3(16, 32), 128, SMEM01>>>(OB, wwo, bwo, TB, 2048, 2048, 2048,
                                             nullptr, nullptr);

    HPtrs6 wp  = {{ WT + 8ull * 1048576, nullptr, nullptr, nullptr, nullptr, nullptr }};
    PtrsB bpp = {{ bp, nullptr, nullptr, nullptr, nullptr, nullptr }};
    gemm_h<2><<<dim3(8, 32), 128, SMEM2>>>(TB, wp, bpp, d_out, 1024, 2048, 1024,
                                           lambda_param, layer_idx);
}

// round 13
// speedup vs baseline: 1.0161x; 1.0161x over previous
#include <cuda_runtime.h>
#include <cuda_fp16.h>
#include <math.h>
#include <stdint.h>

#define Bsz 2
#define Ssz 2048
#define Hsz 16
#define Msz 4096

// fp16 scratch: XH 8MB | WT 18MB | QKV 48MB | OB 16MB | TB 16MB
#define OFF_XH  0ull
#define OFF_WT  8388608ull
#define OFF_QKV 27262976ull
#define OFF_OB  77594624ull
#define OFF_TB  94371840ull
__device__ __align__(1024) unsigned char g_scratch[111149056ull];

// ---------------------------------------------------------------------------
// helpers
// ---------------------------------------------------------------------------
__device__ __forceinline__ uint32_t cvta_smem(const void* p) {
    uint32_t a;
    asm("{ .reg .u64 t; cvta.to.shared.u64 t, %1; cvt.u32.u64 %0, t; }"
        : "=r"(a) : "l"(p));
    return a;
}
__device__ __forceinline__ void cp16(uint32_t dst, const void* src) {
    asm volatile("cp.async.cg.shared.global [%0], [%1], 16;" :: "r"(dst), "l"(src));
}
__device__ __forceinline__ void cp_commit() { asm volatile("cp.async.commit_group;"); }
template <int N>
__device__ __forceinline__ void cp_wait() { asm volatile("cp.async.wait_group %0;" :: "n"(N)); }

__device__ __forceinline__ uint32_t f2h2(float lo, float hi) {
    uint32_t r;
    asm("cvt.rn.f16x2.f32 %0, %2, %1;" : "=r"(r) : "f"(lo), "f"(hi));
    return r;
}
__device__ __forceinline__ float2 h2f2(uint32_t u) {
    __half2 h = *reinterpret_cast<__half2*>(&u);
    return __half22float2(h);
}
__device__ __forceinline__ float ex2f(float x) {
    float r;
    asm("ex2.approx.f32 %0, %1;" : "=f"(r) : "f"(x));
    return r;
}
__device__ __forceinline__ uint32_t ex2h2(uint32_t x) {
    uint32_t r;
    asm("ex2.approx.f16x2 %0, %1;" : "=r"(r) : "r"(x));
    return r;
}

// mma m16n8k16 fp16 in, fp32 accum
__device__ __forceinline__ void mma16(float c[4], const uint32_t a[4],
                                      uint32_t b0, uint32_t b1) {
    asm volatile(
        "mma.sync.aligned.m16n8k16.row.col.f32.f16.f16.f32 "
        "{%0,%1,%2,%3}, {%4,%5,%6,%7}, {%8,%9}, {%0,%1,%2,%3};"
        : "+f"(c[0]), "+f"(c[1]), "+f"(c[2]), "+f"(c[3])
        : "r"(a[0]), "r"(a[1]), "r"(a[2]), "r"(a[3]), "r"(b0), "r"(b1));
}
__device__ __forceinline__ void ldm_x4(uint32_t r[4], uint32_t addr) {
    asm volatile("ldmatrix.sync.aligned.m8n8.x4.shared.b16 {%0,%1,%2,%3}, [%4];"
        : "=r"(r[0]), "=r"(r[1]), "=r"(r[2]), "=r"(r[3]) : "r"(addr));
}
__device__ __forceinline__ void ldm_x4t(uint32_t r[4], uint32_t addr) {
    asm volatile("ldmatrix.sync.aligned.m8n8.x4.trans.shared.b16 {%0,%1,%2,%3}, [%4];"
        : "=r"(r[0]), "=r"(r[1]), "=r"(r[2]), "=r"(r[3]) : "r"(addr));
}

struct PtrsW { const float* p[9]; };
struct PtrsB { const float* p[6]; };
struct HPtrs6 { const __half* p[6]; };

// ---------------------------------------------------------------------------
// prep: z<9: transpose+convert weight z to [n][k] fp16; z==9: convert x fp16
// ---------------------------------------------------------------------------
__global__ __launch_bounds__(256)
void prep_all(PtrsW src, const float4* __restrict__ xin,
              uint32_t* __restrict__ wdst, uint4* __restrict__ xdst)
{
    const int z = blockIdx.z;
    if (z == 9) {
        int bid = blockIdx.y * 32 + blockIdx.x;
        int tid = threadIdx.y * 32 + threadIdx.x;
#pragma unroll
        for (int i = 0; i < 2; i++) {
            int idx = bid * 512 + tid + i * 256;   // 524288 total
            float4 v0 = xin[2 * idx], v1 = xin[2 * idx + 1];
            uint4 o;
            o.x = f2h2(v0.x, v0.y); o.y = f2h2(v0.z, v0.w);
            o.z = f2h2(v1.x, v1.y); o.w = f2h2(v1.z, v1.w);
            xdst[idx] = o;
        }
        return;
    }
    __shared__ float tsm[32][33];
    const float* W = src.p[z];
    uint32_t* out = wdst + (size_t)z * (1024 * 512);
    const int bx = blockIdx.x * 32, by = blockIdx.y * 32;
    const int x = threadIdx.x, y = threadIdx.y;
    for (int i = y; i < 32; i += 8)
        tsm[i][x] = W[(size_t)(by + i) * 1024 + bx + x];
    __syncthreads();
    int tid = y * 32 + x;
#pragma unroll
    for (int s = 0; s < 2; s++) {
        int idx = tid + s * 256;
        int row = idx >> 4, p = idx & 15;
        out[(size_t)(bx + row) * 512 + (by >> 1) + p] =
            f2h2(tsm[2 * p][row], tsm[2 * p + 1][row]);
    }
}

// ---------------------------------------------------------------------------
// fp16 GEMM (R11 config): CTA 128x128, BK=32, 4 warps (warp tile 64x64),
// 3-stage cp.async, 128 threads, 2 CTAs/SM.
// VAR 0/1: ldmatrix fragment loads. VAR 2: scalar path with fused diff.
// ---------------------------------------------------------------------------
#define AW 20
#define BW 20
#define A_U (128 * AW)   // 2560 u32
#define B_U (128 * BW)   // 2560 u32

template <int VAR>
__global__ __launch_bounds__(128, 2)
void gemm_h(const __half* __restrict__ A, HPtrs6 Bp, PtrsB biasP,
            void* __restrict__ Cout, int N, int lda, int ldc,
            const float* __restrict__ lambda_param,
            const unsigned* __restrict__ layer_idx_bits)
{
    constexpr int A_ST = (VAR == 2) ? 2 * A_U : A_U;
    constexpr int STG = A_ST + B_U;
    extern __shared__ uint32_t smu[];
    const uint32_t sbase = cvta_smem(smu);

    const int tid = threadIdx.x;
    const int lane = tid & 31;
    const int g = lane >> 2, t = lane & 3;
    const int lrow = lane & 7, lsel = lane >> 3;
    const int wid = tid >> 5;
    const int wm = wid >> 1, wn = wid & 1;       // 2 x 2 warp grid, 64x64 tiles
    const int m0 = blockIdx.y * 128, n0 = blockIdx.x * 128;
    const int j = n0 >> 10, nn = n0 & 1023;
    const int aoffr = (VAR == 1) ? (j << 10) : 0;

    float lam = 0.f;
    if (VAR == 2) {
        unsigned bits = *layer_idx_bits;
        float lf = (bits < 10000u) ? (float)bits : __uint_as_float(bits);
        float e = __expf(-0.3f * fmaxf(lf - 1.0f, 0.0f));
        lam = fminf(fmaxf((0.8f - 0.6f * e) * lambda_param[0], 0.1f), 0.9f);
    }

    const __half* Bj = Bp.p[j];
    float c[4][8][4] = {};

    const uint32_t aoff = (uint32_t)((wm * 64 + ((lsel & 1) ? 8 : 0) + lrow) * AW
                                     + ((lsel >> 1) ? 4 : 0)) * 4u;
    const uint32_t boff = (uint32_t)((wn * 64 + ((lsel >> 1) ? 8 : 0) + lrow) * BW
                                     + ((lsel & 1) ? 4 : 0)) * 4u;

    auto loadTile = [&](int stg, int kt) {
        uint32_t sa = sbase + (uint32_t)(stg * STG) * 4u;
        uint32_t sb = sa + (uint32_t)A_ST * 4u;
#pragma unroll
        for (int i = 0; i < 4; i++) {
            int idx = tid + i * 128;
            int row = idx >> 2, ch = idx & 3;
            const __half* src = A + (size_t)(m0 + row) * lda + aoffr + kt * 32 + ch * 8;
            cp16(sa + (uint32_t)(row * AW + ch * 4) * 4u, src);
            if (VAR == 2)
                cp16(sa + (uint32_t)(A_U + row * AW + ch * 4) * 4u, src + 1024);
        }
#pragma unroll
        for (int i = 0; i < 4; i++) {
            int idx = tid + i * 128;
            int row = idx >> 2, ch = idx & 3;
            cp16(sb + (uint32_t)(row * BW + ch * 4) * 4u,
                 Bj + (size_t)(nn + row) * 1024 + kt * 32 + ch * 8);
        }
        cp_commit();
    };

    const int T = 32;
    loadTile(0, 0); loadTile(1, 1);

    for (int kt = 0; kt < T; kt++) {
        const int stg = kt % 3;
        if (kt < T - 1) cp_wait<1>(); else cp_wait<0>();
        __syncthreads();
        if (kt + 2 < T) loadTile((kt + 2) % 3, kt + 2);

        if (VAR == 2) {
            const uint32_t* Au = smu + stg * STG;
            const uint32_t* Bu = Au + A_ST;
#pragma unroll
            for (int kf = 0; kf < 2; kf++) {
                uint32_t a[4][4];
#pragma unroll
                for (int mf = 0; mf < 4; mf++) {
                    int rb = wm * 64 + mf * 16;
#pragma unroll
                    for (int q = 0; q < 4; q++) {
                        int r = rb + g + ((q & 1) ? 8 : 0);
                        int kp = kf * 8 + t + ((q >> 1) ? 4 : 0);
                        float2 fu = h2f2(Au[r * AW + kp]);
                        float2 fv = h2f2(Au[A_U + r * AW + kp]);
                        a[mf][q] = f2h2(fmaf(-lam, fv.x, fu.x), fmaf(-lam, fv.y, fu.y));
                    }
                }
#pragma unroll
                for (int nf = 0; nf < 8; nf++) {
                    int n = wn * 64 + nf * 8 + g;
                    uint32_t b0 = Bu[n * BW + kf * 8 + t];
                    uint32_t b1 = Bu[n * BW + kf * 8 + 4 + t];
#pragma unroll
                    for (int mf = 0; mf < 4; mf++)
                        mma16(c[mf][nf], a[mf], b0, b1);
                }
            }
        } else {
            uint32_t aS = sbase + (uint32_t)(stg * STG) * 4u + aoff;
            uint32_t bS = sbase + (uint32_t)(stg * STG + A_ST) * 4u + boff;
#pragma unroll
            for (int kf = 0; kf < 2; kf++) {
                uint32_t a[4][4], bq[4][4];
#pragma unroll
                for (int mf = 0; mf < 4; mf++)
                    ldm_x4(a[mf], aS + (uint32_t)(mf * 16 * AW) * 4u + kf * 32u);
#pragma unroll
                for (int i = 0; i < 4; i++)
                    ldm_x4(bq[i], bS + (uint32_t)(i * 16 * BW) * 4u + kf * 32u);
#pragma unroll
                for (int i = 0; i < 4; i++)
#pragma unroll
                    for (int mf = 0; mf < 4; mf++) {
                        mma16(c[mf][2 * i],     a[mf], bq[i][0], bq[i][1]);
                        mma16(c[mf][2 * i + 1], a[mf], bq[i][2], bq[i][3]);
                    }
            }
        }
    }

    const float* bb = biasP.p[j] + nn;
#pragma unroll
    for (int mf = 0; mf < 4; mf++) {
        int r0 = m0 + wm * 64 + mf * 16 + g;
#pragma unroll
        for (int nf = 0; nf < 8; nf++) {
            int cl = wn * 64 + nf * 8 + 2 * t;
            float bv0 = bb[cl], bv1 = bb[cl + 1];
            float v00 = c[mf][nf][0] + bv0, v01 = c[mf][nf][1] + bv1;
            float v10 = c[mf][nf][2] + bv0, v11 = c[mf][nf][3] + bv1;
            if (VAR == 2) {
                float* C = (float*)Cout;
                *(float2*)(C + (size_t)r0 * ldc + n0 + cl) = make_float2(v00, v01);
                *(float2*)(C + (size_t)(r0 + 8) * ldc + n0 + cl) = make_float2(v10, v11);
            } else {
                uint32_t* C = (uint32_t*)Cout;
                int lp = ldc >> 1;
                C[(size_t)r0 * lp + ((n0 + cl) >> 1)] = f2h2(v00, v01);
                C[(size_t)(r0 + 8) * lp + ((n0 + cl) >> 1)] = f2h2(v10, v11);
            }
        }
    }
}

// ---------------------------------------------------------------------------
// fp16 flash attention: 4 warps x 32 q-rows, 128 q-rows/CTA, 2 CTAs/SM.
// 3-stage KV pipeline (prefetch 2 tiles ahead, cp_wait<1>).
// P in registers; f16x2 exp; ones-MMA row sums; lazy rescale.
// ---------------------------------------------------------------------------
#define KWu 36
#define KSTGu (64 * KWu)
#define ATT_SMEM (6 * KSTGu * 4)   // 55296 B (K + V triple-buffered)

__global__ __launch_bounds__(128, 2)
void flash_h(const __half* __restrict__ QKV, __half* __restrict__ OB)
{
    extern __shared__ uint32_t smu[];
    const uint32_t sbase = cvta_smem(smu);
    const uint32_t sK = sbase;                                  // 3 x KSTGu
    const uint32_t sV = sbase + (uint32_t)(3 * KSTGu) * 4u;     // 3 x KSTGu

    const int tid = threadIdx.x;
    const int w = tid >> 5, lane = tid & 31;
    const int g = lane >> 2, t = lane & 3;
    const int sel = lane >> 3, r8 = lane & 7;
    const int b = blockIdx.y >> 4, h = blockIdx.y & 15, z = blockIdx.z;
    const int q0 = blockIdx.x * 128;
    const size_t ld = 6144;

    const size_t base = (size_t)b * Ssz * ld + (size_t)z * 3072 + h * 64;
    const __half* Kg = QKV + base + 1024;
    const __half* Vg = QKV + base + 2048;

    // Q scale = log2(e)/8 : softmax runs in exp2 domain
    const __half2 scq = __float2half2_rn(0.18033688f);
    uint32_t qf[2][4][4];
#pragma unroll
    for (int mf = 0; mf < 2; mf++) {
#pragma unroll
        for (int q = 0; q < 4; q++) {
            int row = q0 + w * 32 + mf * 16 + g + ((q & 1) ? 8 : 0);
            const __half2* Q2 = (const __half2*)QKV + ((base + (size_t)row * ld) >> 1);
#pragma unroll
            for (int kf = 0; kf < 4; kf++) {
                __half2 v = __hmul2(Q2[kf * 8 + t + ((q >> 1) ? 4 : 0)], scq);
                qf[mf][kf][q] = *(uint32_t*)&v;
            }
        }
    }

    float o[2][8][4] = {};
    float lc[2][4] = {};
    float mm[2][2] = { {-1e30f, -1e30f}, {-1e30f, -1e30f} };
    const uint32_t ONE2 = 0x3C003C00u;

    auto loadKV = [&](int buf, int tile) {
#pragma unroll
        for (int i = 0; i < 4; i++) {
            int idx = tid + i * 128;
            int row = idx >> 3, ch = idx & 7;
            size_t off = (size_t)(tile * 64 + row) * ld + ch * 8;
            cp16(sK + (uint32_t)(buf * KSTGu + row * KWu + ch * 4) * 4u, Kg + off);
            cp16(sV + (uint32_t)(buf * KSTGu + row * KWu + ch * 4) * 4u, Vg + off);
        }
        cp_commit();
    };

    const int NT = Ssz / 64;
    loadKV(0, 0); loadKV(1, 1);

    const int rowB = (sel >= 2) ? 8 : 0, colB = (sel & 1) ? 4 : 0;
    const int rowA = (sel & 1) ? 8 : 0, colA = (sel >= 2) ? 4 : 0;

    for (int tile = 0; tile < NT; tile++) {
        const int buf = tile % 3;
        if (tile + 1 < NT) cp_wait<1>(); else cp_wait<0>();
        __syncthreads();
        if (tile + 2 < NT) loadKV((tile + 2) % 3, tile + 2);

        const uint32_t sKb = sK + (uint32_t)(buf * KSTGu) * 4u;
        const uint32_t sVb = sV + (uint32_t)(buf * KSTGu) * 4u;

        // S = Q K^T (32 x 64 per warp; K frags shared across both m-frags)
        float s[2][8][4] = {};
#pragma unroll
        for (int kf = 0; kf < 4; kf++) {
#pragma unroll
            for (int np = 0; np < 4; np++) {
                uint32_t kb[4];
                ldm_x4(kb, sKb + (uint32_t)((np * 16 + rowB + r8) * KWu + kf * 8 + colB) * 4u);
                mma16(s[0][2 * np],     qf[0][kf], kb[0], kb[1]);
                mma16(s[0][2 * np + 1], qf[0][kf], kb[2], kb[3]);
                mma16(s[1][2 * np],     qf[1][kf], kb[0], kb[1]);
                mma16(s[1][2 * np + 1], qf[1][kf], kb[2], kb[3]);
            }
        }

        // online softmax per m-fragment; P packed directly into A-fragments
        uint32_t pa[2][4][4];
#pragma unroll
        for (int mf = 0; mf < 2; mf++) {
            float tmax0 = -1e30f, tmax1 = -1e30f;
#pragma unroll
            for (int nf = 0; nf < 8; nf++) {
                tmax0 = fmaxf(tmax0, fmaxf(s[mf][nf][0], s[mf][nf][1]));
                tmax1 = fmaxf(tmax1, fmaxf(s[mf][nf][2], s[mf][nf][3]));
            }
            tmax0 = fmaxf(tmax0, __shfl_xor_sync(0xffffffffu, tmax0, 1));
            tmax0 = fmaxf(tmax0, __shfl_xor_sync(0xffffffffu, tmax0, 2));
            tmax1 = fmaxf(tmax1, __shfl_xor_sync(0xffffffffu, tmax1, 1));
            tmax1 = fmaxf(tmax1, __shfl_xor_sync(0xffffffffu, tmax1, 2));

            float mn0 = fmaxf(mm[mf][0], tmax0), mn1 = fmaxf(mm[mf][1], tmax1);

#pragma unroll
            for (int nf = 0; nf < 8; nf++) {
                uint32_t p01 = ex2h2(f2h2(s[mf][nf][0] - mn0, s[mf][nf][1] - mn0));
                uint32_t p23 = ex2h2(f2h2(s[mf][nf][2] - mn1, s[mf][nf][3] - mn1));
                pa[mf][nf >> 1][(nf & 1) * 2 + 0] = p01;
                pa[mf][nf >> 1][(nf & 1) * 2 + 1] = p23;
            }

            bool moved = !__all_sync(0xffffffffu, (mn0 == mm[mf][0]) & (mn1 == mm[mf][1]));
            if (moved) {
                float al0 = ex2f(mm[mf][0] - mn0), al1 = ex2f(mm[mf][1] - mn1);
                lc[mf][0] *= al0; lc[mf][2] *= al1;
#pragma unroll
                for (int nf = 0; nf < 8; nf++) {
                    o[mf][nf][0] *= al0; o[mf][nf][1] *= al0;
                    o[mf][nf][2] *= al1; o[mf][nf][3] *= al1;
                }
            }
            mm[mf][0] = mn0; mm[mf][1] = mn1;
        }

        // l += row-sums of P (ones-MMA)
#pragma unroll
        for (int kf = 0; kf < 4; kf++) {
            mma16(lc[0], pa[0][kf], ONE2, ONE2);
            mma16(lc[1], pa[1][kf], ONE2, ONE2);
        }

        // O += P V (V frags shared across both m-frags)
#pragma unroll
        for (int kf = 0; kf < 4; kf++) {
#pragma unroll
            for (int np = 0; np < 4; np++) {
                uint32_t vb[4];
                ldm_x4t(vb, sVb + (uint32_t)((kf * 16 + rowA + r8) * KWu + np * 8 + colA) * 4u);
                mma16(o[0][2 * np],     pa[0][kf], vb[0], vb[1]);
                mma16(o[0][2 * np + 1], pa[0][kf], vb[2], vb[3]);
                mma16(o[1][2 * np],     pa[1][kf], vb[0], vb[1]);
                mma16(o[1][2 * np + 1], pa[1][kf], vb[2], vb[3]);
            }
        }
    }

    uint32_t* O2 = (uint32_t*)OB;
#pragma unroll
    for (int mf = 0; mf < 2; mf++) {
        float inv0 = 1.f / lc[mf][0], inv1 = 1.f / lc[mf][2];
        int row = q0 + w * 32 + mf * 16 + g;
        size_t rb0 = (size_t)(b * Ssz + row) * 1024 + z * 512 + h * 32;
        size_t rb1 = rb0 + 8 * 1024;
#pragma unroll
        for (int nf = 0; nf < 8; nf++) {
            O2[rb0 + nf * 4 + t] = f2h2(o[mf][nf][0] * inv0, o[mf][nf][1] * inv0);
            O2[rb1 + nf * 4 + t] = f2h2(o[mf][nf][2] * inv1, o[mf][nf][3] * inv1);
        }
    }
}

// ---------------------------------------------------------------------------
extern "C" void kernel_launch(void* const* d_in, const int* in_sizes, int n_in,
                              void* d_out, int out_size)
{
    const float*    x            = (const float*)d_in[0];
    const unsigned* layer_idx    = (const unsigned*)d_in[1];
    const float*    lambda_param = (const float*)d_in[2];

    const float *Wq1, *bq1, *Wk1, *bk1, *Wv1, *bv1, *Wo1, *bo1;
    const float *Wq2, *bq2, *Wk2, *bk2, *Wv2, *bv2, *Wo2, *bo2;

    bool sig_order = (in_sizes[4] < 100000);
    if (!sig_order) {
        Wq1 = (const float*)d_in[3];  Wk1 = (const float*)d_in[4];
        Wv1 = (const float*)d_in[5];  Wo1 = (const float*)d_in[6];
        bq1 = (const float*)d_in[7];  bk1 = (const float*)d_in[8];
        bv1 = (const float*)d_in[9];  bo1 = (const float*)d_in[10];
        Wq2 = (const float*)d_in[11]; Wk2 = (const float*)d_in[12];
        Wv2 = (const float*)d_in[13]; Wo2 = (const float*)d_in[14];
        bq2 = (const float*)d_in[15]; bk2 = (const float*)d_in[16];
        bv2 = (const float*)d_in[17]; bo2 = (const float*)d_in[18];
    } else {
        Wq1 = (const float*)d_in[3];  bq1 = (const float*)d_in[4];
        Wk1 = (const float*)d_in[5];  bk1 = (const float*)d_in[6];
        Wv1 = (const float*)d_in[7];  bv1 = (const float*)d_in[8];
        Wo1 = (const float*)d_in[9];  bo1 = (const float*)d_in[10];
        Wq2 = (const float*)d_in[11]; bq2 = (const float*)d_in[12];
        Wk2 = (const float*)d_in[13]; bk2 = (const float*)d_in[14];
        Wv2 = (const float*)d_in[15]; bv2 = (const float*)d_in[16];
        Wo2 = (const float*)d_in[17]; bo2 = (const float*)d_in[18];
    }
    const float* Wp = (const float*)d_in[19];
    const float* bp = (const float*)d_in[20];

    unsigned char* sc = nullptr;
    cudaGetSymbolAddress((void**)&sc, g_scratch);
    __half* XH  = (__half*)(sc + OFF_XH);
    __half* WT  = (__half*)(sc + OFF_WT);
    __half* QKV = (__half*)(sc + OFF_QKV);
    __half* OB  = (__half*)(sc + OFF_OB);
    __half* TB  = (__half*)(sc + OFF_TB);

    const int SMEM01 = 3 * (A_U + B_U) * 4;       // 61440
    const int SMEM2  = 3 * (2 * A_U + B_U) * 4;   // 92160

    cudaFuncSetAttribute(gemm_h<0>, cudaFuncAttributeMaxDynamicSharedMemorySize, SMEM01);
    cudaFuncSetAttribute(gemm_h<1>, cudaFuncAttributeMaxDynamicSharedMemorySize, SMEM01);
    cudaFuncSetAttribute(gemm_h<2>, cudaFuncAttributeMaxDynamicSharedMemorySize, SMEM2);
    cudaFuncSetAttribute(flash_h,   cudaFuncAttributeMaxDynamicSharedMemorySize, ATT_SMEM);

    PtrsW srcW = {{ Wq1, Wk1, Wv1, Wq2, Wk2, Wv2, Wo1, Wo2, Wp }};
    prep_all<<<dim3(32, 32, 10), dim3(32, 8)>>>(srcW, (const float4*)x,
                                                (uint32_t*)WT, (uint4*)XH);

    HPtrs6 wqkv = {{ WT + 0ull * 1048576, WT + 1ull * 1048576, WT + 2ull * 1048576,
                     WT + 3ull * 1048576, WT + 4ull * 1048576, WT + 5ull * 1048576 }};
    PtrsB bqkv = {{ bq1, bk1, bv1, bq2, bk2, bv2 }};
    gemm_h<0><<<dim3(48, 32), 128, SMEM01>>>(XH, wqkv, bqkv, QKV, 6144, 1024, 6144,
                                             nullptr, nullptr);

    flash_h<<<dim3(Ssz / 128, Bsz * Hsz, 2), 128, ATT_SMEM>>>(QKV, OB);

    HPtrs6 wwo = {{ WT + 6ull * 1048576, WT + 7ull * 1048576, nullptr, nullptr, nullptr, nullptr }};
    PtrsB bwo = {{ bo1, bo2, nullptr, nullptr, nullptr, nullptr }};
    gemm_h<1><<<dim3(16, 32), 128, SMEM01>>>(OB, wwo, bwo, TB, 2048, 2048, 2048,
                                             nullptr, nullptr);

    HPtrs6 wp  = {{ WT + 8ull * 1048576, nullptr, nullptr, nullptr, nullptr, nullptr }};
    PtrsB bpp = {{ bp, nullptr, nullptr, nullptr, nullptr, nullptr }};
    gemm_h<2><<<dim3(8, 32), 128, SMEM2>>>(TB, wp, bpp, d_out, 1024, 2048, 1024,
                                           lambda_param, layer_idx);
}